// round 17
// baseline (speedup 1.0000x reference)
#include <cuda_runtime.h>
#include <cuda_fp16.h>
#include <cstdint>

#define NB    16
#define NDIM  128
#define NPTS  16384
#define NJ    16
#define NR    8
#define KT    32                     // K-tile depth
#define TILE_B (128 * 40 * 2)        // 10240 bytes per fp16 tile (80B rows)
#define WSCALE 16384.0f
#define WINV   (1.0f / 16384.0f)

typedef __half hf;

// ---------------- device scratch ----------------
__device__ __align__(16) float g_xhatT[NB * 128 * 128];      // [b][l][i]  1 MB
__device__ __align__(16) float g_y    [NB * 128 * 128];      // [(b,o)][k] 1 MB (scaled 2^14)
__device__ __align__(16) hf g_xhT_h[NB * 128 * 128];         // [b][l][i]
__device__ __align__(16) hf g_Wt_h [NJ * 128 * 128];         // [j][o][i] (x 2^14)
__device__ __align__(16) hf g_Hk_h [128 * NJ * 128];         // [k][(j,l)]
__device__ __align__(16) hf g_y_h  [2048 * 128];             // descaled fp16
__device__ __align__(16) hf g_wbT_h[128 * NPTS];             // [l][x]
__device__ __align__(16) hf g_bs_h [NPTS * 128];             // [x][k]

// ---------------- helpers ----------------
__device__ __forceinline__ uint32_t smem_u32(const void* p) {
    uint32_t a;
    asm("{ .reg .u64 t; cvta.to.shared.u64 t, %1; cvt.u32.u64 %0, t; }" : "=r"(a) : "l"(p));
    return a;
}
__device__ __forceinline__ void cp16(uint32_t dst, const void* src) {
    asm volatile("cp.async.cg.shared.global [%0], [%1], 16;" :: "r"(dst), "l"(src));
}
__device__ __forceinline__ void cp_commit() {
    asm volatile("cp.async.commit_group;" ::: "memory");
}
template <int N>
__device__ __forceinline__ void cp_wait() {
    asm volatile("cp.async.wait_group %0;" :: "n"(N) : "memory");
}
__device__ __forceinline__ void ldmx4(uint32_t* r, uint32_t addr) {
    asm volatile("ldmatrix.sync.aligned.m8n8.x4.shared.b16 {%0,%1,%2,%3}, [%4];"
                 : "=r"(r[0]), "=r"(r[1]), "=r"(r[2]), "=r"(r[3]) : "r"(addr));
}
__device__ __forceinline__ void mma_f16(float* c, const uint32_t* a, const uint32_t* b) {
    asm volatile("mma.sync.aligned.m16n8k16.row.col.f32.f16.f16.f32 "
                 "{%0,%1,%2,%3}, {%4,%5,%6,%7}, {%8,%9}, {%0,%1,%2,%3};"
                 : "+f"(c[0]), "+f"(c[1]), "+f"(c[2]), "+f"(c[3])
                 : "r"(a[0]), "r"(a[1]), "r"(a[2]), "r"(a[3]), "r"(b[0]), "r"(b[1]));
}
__device__ __forceinline__ uint2 cvt_h4(float4 v) {
    __half2 h0 = __floats2half2_rn(v.x, v.y);
    __half2 h1 = __floats2half2_rn(v.z, v.w);
    return make_uint2(*(uint32_t*)&h0, *(uint32_t*)&h1);
}
__device__ __forceinline__ uint2 cvt_h4s(float4 v, float s) {
    return cvt_h4(make_float4(v.x * s, v.y * s, v.z * s, v.w * s));
}

// ---------------- 1-term 32-deep K-tile compute: A at abase, B at bbase ----------
__device__ __forceinline__ void compute_ab(uint32_t abase, uint32_t bbase,
                                           float acc[16][4],
                                           int a_off, int b_off, int wr, int wc) {
#pragma unroll
    for (int ks = 0; ks < 2; ++ks) {
        const uint32_t koff = ks * 32;
        uint32_t bh[4][2];
#pragma unroll
        for (int n2 = 0; n2 < 2; ++n2) {
            uint32_t r4[4];
            ldmx4(r4, bbase + (wc * 32 + n2 * 16) * 80 + koff + b_off);
            bh[n2 * 2][0] = r4[0]; bh[n2 * 2][1] = r4[1];
            bh[n2 * 2 + 1][0] = r4[2]; bh[n2 * 2 + 1][1] = r4[3];
        }
#pragma unroll
        for (int mi = 0; mi < 4; ++mi) {
            uint32_t ah[4];
            ldmx4(ah, abase + (wr * 64 + mi * 16) * 80 + koff + a_off);
#pragma unroll
            for (int ni = 0; ni < 4; ++ni)
                mma_f16(acc[mi * 4 + ni], ah, bh[ni]);
        }
    }
}

// issue cp.async for one fp16 tile (2x16B chunks/thread; 64B data per 80B row)
__device__ __forceinline__ void issue_tile(uint32_t bb, const hf* base,
                                           int ld, int k0, int t) {
    int row = t >> 2, q = t & 3;
    cp16(bb + row * 80 + q * 16, base + (size_t)row * ld + k0 + q * 8);
    row = (t + 256) >> 2; q = (t + 256) & 3;
    cp16(bb + row * 80 + q * 16, base + (size_t)row * ld + k0 + q * 8);
}

// ---------------- flat K=128 helpers: interleaved [A_kt | B_kt] x 4 = 81920 B ------
__device__ __forceinline__ void flat_load(uint32_t sb, const hf* A, int lda,
                                          const hf* B, int ldb, int t) {
#pragma unroll
    for (int kt = 0; kt < 4; ++kt) {
        issue_tile(sb + kt * 2 * TILE_B, A, lda, kt * KT, t);
        issue_tile(sb + kt * 2 * TILE_B + TILE_B, B, ldb, kt * KT, t);
    }
    cp_commit();
}
__device__ __forceinline__ void flat_compute(uint32_t sb, float acc[16][4],
                                             int a_off, int b_off, int wr, int wc) {
#pragma unroll
    for (int kt = 0; kt < 4; ++kt)
        compute_ab(sb + kt * 2 * TILE_B, sb + kt * 2 * TILE_B + TILE_B,
                   acc, a_off, b_off, wr, wc);
}
#define FLAT_SMEM (8 * TILE_B)   // 81920

// ---------------- fused prep kernel ----------------
#define WT_B0  16
#define TWB_B0 1040
#define TBS_B0 1552
__global__ void __launch_bounds__(256) prep_kernel(const float* __restrict__ Aop,
                                                   const float* __restrict__ Bop,
                                                   const float* __restrict__ Dout,
                                                   const float* __restrict__ Din,
                                                   const float* __restrict__ product,
                                                   const float* __restrict__ wgt,
                                                   const float* __restrict__ wb,
                                                   const float* __restrict__ bases) {
    __shared__ float sm[5120];   // 20 KB
    const int bid = blockIdx.x;
    const int t = threadIdx.x;

    if (bid < WT_B0) {
        const int j = bid;
        float* Aj = sm;
        float* Bj = sm + 512;
        float* Qs = sm + 1024;
        for (int i = t; i < NR * 64; i += 256) {
            Aj[i] = Aop[j * (NR * 64) + i];
            Bj[i] = Bop[j * (NR * 64) + i];
        }
        __syncthreads();
#pragma unroll
        for (int s = 0; s < 16; ++s) {
            int idx = t + 256 * s;
            int m = idx >> 6, n = idx & 63;
            float q = 0.0f;
#pragma unroll
            for (int r = 0; r < NR; ++r) q += Aj[r * 64 + m] * Bj[r * 64 + n];
            Qs[idx] = q;
        }
        __syncthreads();
#pragma unroll 4
        for (int s = 0; s < 64; ++s) {
            int idx = t + 256 * s;        // 16384 = 128x128
            int k = idx >> 7, l = idx & 127;
            float h = Dout[j * 128 + k] * Din[j * 128 + l] * product[k * 128 + l];
            if (k < 64 && l < 64) h += Qs[k * 64 + l];
            g_Hk_h[k * (NJ * 128) + j * 128 + l] = __float2half_rn(h);
        }
    } else if (bid < TWB_B0) {
        int id = (bid - WT_B0) * 256 + t;   // 262144
        g_xhatT[id] = 0.0f;
        g_y[id]     = 0.0f;
        int ii = id & 127;
        int o  = (id >> 7) & 127;
        int j  = id >> 14;
        g_Wt_h[id] = __float2half_rn(wgt[(ii * 128 + o) * NJ + j] * WSCALE);
    } else if (bid < TBS_B0) {
        const int bt = bid - TWB_B0;        // 0..511
        const int xb = (bt >> 2) * 128;
        const int kb = (bt & 3) * 32;
        const int q  = t & 7;
#pragma unroll
        for (int p = 0; p < 4; ++p) {
            const int xr = p * 32 + (t >> 3);
            float4 v = *(const float4*)&wb[(size_t)(xb + xr) * 128 + kb + q * 4];
            sm[(q * 4 + 0) * 129 + xr] = v.x;
            sm[(q * 4 + 1) * 129 + xr] = v.y;
            sm[(q * 4 + 2) * 129 + xr] = v.z;
            sm[(q * 4 + 3) * 129 + xr] = v.w;
        }
        __syncthreads();
        const int kr = t >> 3;
        const int xq = (t & 7) * 16;
        const float* row = &sm[kr * 129 + xq];
        uint32_t pk[8];
#pragma unroll
        for (int m = 0; m < 8; ++m) {
            __half2 h = __floats2half2_rn(row[2 * m], row[2 * m + 1]);
            pk[m] = *(uint32_t*)&h;
        }
        hf* dst = &g_wbT_h[(size_t)(kb + kr) * NPTS + xb + xq];
        *(uint4*)dst       = make_uint4(pk[0], pk[1], pk[2], pk[3]);
        *(uint4*)(dst + 8) = make_uint4(pk[4], pk[5], pk[6], pk[7]);
    } else {
        const int bt = bid - TBS_B0;        // 0..511
#pragma unroll
        for (int s = 0; s < 4; ++s) {
            int i4 = bt * 256 + t + s * 131072;
            float4 v = ((const float4*)bases)[i4];
            *(uint2*)&g_bs_h[(size_t)i4 * 4] = cvt_h4(v);
        }
    }
}

// xhatT fp32 -> fp16 hi
__global__ void __launch_bounds__(256) cvt0_kernel() {
    int i4 = blockIdx.x * 256 + threadIdx.x;
    float4 v = ((const float4*)g_xhatT)[i4];
    *(uint2*)&g_xhT_h[(size_t)i4 * 4] = cvt_h4(v);
}

// y fp32 (scaled) -> fp16 descaled
__global__ void __launch_bounds__(256) cvty_kernel() {
    int i4 = blockIdx.x * 256 + threadIdx.x;
    float4 v = ((const float4*)g_y)[i4];
    *(uint2*)&g_y_h[(size_t)i4 * 4] = cvt_h4s(v, WINV);
}

// ---------------- stage A: smem-staged fp32 conversion, 2 CTAs/SM ----------------
// smem: [0, 2*XS_B) fp32 x staging (144B rows); [XA, +2*TILE_B) A fp16;
//       [XB, +2*TILE_B) B fp16.  Total 77824 B -> 2 CTAs/SM.
#define XS_ROW 144
#define XS_B   (128 * XS_ROW)          // 18432
#define XA_OFF (2 * XS_B)              // 36864
#define XB_OFF (XA_OFF + 2 * TILE_B)   // 57344
#define A_SMEM (XB_OFF + 2 * TILE_B)   // 77824

__device__ __forceinline__ void a_issue(uint32_t sb, int buf,
                                        const float* A, const hf* B, int k0, int t) {
    // x fp32 tile: 128 rows x 32 floats = 1024 x 16B chunks
#pragma unroll
    for (int i = 0; i < 4; ++i) {
        const int idx = t + 256 * i, row = idx >> 3, q = idx & 7;
        cp16(sb + buf * XS_B + row * XS_ROW + q * 16,
             A + (size_t)row * NPTS + k0 + q * 4);
    }
    // wbT fp16 tile
    issue_tile(sb + XB_OFF + buf * TILE_B, B, NPTS, k0, t);
    cp_commit();
}

__global__ void __launch_bounds__(256, 2) k_mm_a(const float* __restrict__ x) {
    extern __shared__ __align__(128) char dsm[];
    const int b  = blockIdx.x;
    const int ks = blockIdx.y;                 // 16 splits x 1024 K
    const float* A = x + (size_t)(b * 128) * NPTS + ks * 1024;
    const hf*    B = g_wbT_h + ks * 1024;
    const int t = threadIdx.x, lane = t & 31, w = t >> 5;
    const int wr = w >> 2, wc = w & 3;
    const uint32_t sb = smem_u32(dsm);
    const int a_off = ((lane & 7) + ((lane >> 3) & 1) * 8) * 80 + ((lane >> 4) & 1) * 16;
    const int b_off = ((lane & 7) + ((lane >> 4) & 1) * 8) * 80 + ((lane >> 3) & 1) * 16;

    float acc[16][4];
#pragma unroll
    for (int i = 0; i < 16; ++i)
#pragma unroll
        for (int q = 0; q < 4; ++q) acc[i][q] = 0.0f;

    a_issue(sb, 0, A, B, 0, t);

    int cur = 0;
    for (int kt = 0; kt < 32; ++kt) {
        cp_wait<0>();
        __syncthreads();   // loads of cur arrived; prior compute (kt-1) done
        // convert x fp32 staging -> fp16 A tile
#pragma unroll
        for (int i = 0; i < 4; ++i) {
            const int idx = t + 256 * i, r = idx >> 3, c4 = (idx & 7) << 2;
            float4 v = *(const float4*)(dsm + cur * XS_B + r * XS_ROW + c4 * 4);
            *(uint2*)(dsm + XA_OFF + cur * TILE_B + r * 80 + c4 * 2) = cvt_h4(v);
        }
        if (kt + 1 < 32) a_issue(sb, cur ^ 1, A, B, (kt + 1) * KT, t);
        __syncthreads();   // conversion visible
        compute_ab(sb + XA_OFF + cur * TILE_B, sb + XB_OFF + cur * TILE_B,
                   acc, a_off, b_off, wr, wc);
        cur ^= 1;
    }

    float* dst = g_xhatT + (size_t)b * 16384;
#pragma unroll
    for (int mi = 0; mi < 4; ++mi)
#pragma unroll
        for (int ni = 0; ni < 4; ++ni) {
            const int row = wr * 64 + mi * 16 + (lane >> 2);   // i
            const int col = wc * 32 + ni * 8 + (lane & 3) * 2; // l
            const float* a = acc[mi * 4 + ni];
            atomicAdd(&dst[(col + 0) * 128 + row],     a[0]);
            atomicAdd(&dst[(col + 1) * 128 + row],     a[1]);
            atomicAdd(&dst[(col + 0) * 128 + row + 8], a[2]);
            atomicAdd(&dst[(col + 1) * 128 + row + 8], a[3]);
        }
}

// ---------------- fused stage ZY (flat, as R16) ----------------
__global__ void __launch_bounds__(256, 2) k_mm_zy() {
    extern __shared__ __align__(128) char dsm[];
    const int b = blockIdx.x >> 4, j = blockIdx.x & 15;
    const int t = threadIdx.x, lane = t & 31, w = t >> 5;
    const int wr = w >> 2, wc = w & 3;
    const uint32_t sb = smem_u32(dsm);
    const int a_off = ((lane & 7) + ((lane >> 3) & 1) * 8) * 80 + ((lane >> 4) & 1) * 16;
    const int b_off = ((lane & 7) + ((lane >> 4) & 1) * 8) * 80 + ((lane >> 3) & 1) * 16;

    float acc[16][4];
#pragma unroll
    for (int i = 0; i < 16; ++i)
#pragma unroll
        for (int q = 0; q < 4; ++q) acc[i][q] = 0.0f;

    // ---- Phase 1: GEMM1 = Wt_h[j] @ xhat_h[b] ----
    flat_load(sb, g_Wt_h + (size_t)j * 16384, 128,
              g_xhT_h + (size_t)b * 16384, 128, t);
    cp_wait<0>();
    __syncthreads();
    flat_compute(sb, acc, a_off, b_off, wr, wc);
    __syncthreads();   // all warps done reading W/X tiles

    // ---- Phase 2 staging: ztile -> A-slots; Hk -> B-slots ----
#pragma unroll
    for (int mi = 0; mi < 4; ++mi)
#pragma unroll
        for (int ni = 0; ni < 4; ++ni) {
            const int row = wr * 64 + mi * 16 + (lane >> 2);      // o
            const int tc  = (ni * 8 + (lane & 3) * 2) * 2;        // byte col within tile
            const uint32_t hoff = wc * 2 * TILE_B + row * 80 + tc;   // A-slot of tile wc
            const float* a = acc[mi * 4 + ni];
            __half2 h0 = __floats2half2_rn(a[0], a[1]);
            __half2 h1 = __floats2half2_rn(a[2], a[3]);
            *(uint32_t*)(dsm + hoff)          = *(uint32_t*)&h0;
            *(uint32_t*)(dsm + hoff + 8 * 80) = *(uint32_t*)&h1;
        }
    const hf* Bh = g_Hk_h + j * 128;     // rows k, stride 2048
#pragma unroll
    for (int kt = 0; kt < 4; ++kt)
        issue_tile(sb + kt * 2 * TILE_B + TILE_B, Bh, 2048, kt * KT, t);
    cp_commit();

#pragma unroll
    for (int i = 0; i < 16; ++i)
#pragma unroll
        for (int q = 0; q < 4; ++q) acc[i][q] = 0.0f;

    cp_wait<0>();
    __syncthreads();
    flat_compute(sb, acc, a_off, b_off, wr, wc);

#pragma unroll
    for (int mi = 0; mi < 4; ++mi)
#pragma unroll
        for (int ni = 0; ni < 4; ++ni) {
            const int row = b * 128 + wr * 64 + mi * 16 + (lane >> 2);  // (b,o)
            const int col = wc * 32 + ni * 8 + (lane & 3) * 2;          // k
            const float* a = acc[mi * 4 + ni];
            atomicAdd(&g_y[(size_t)row * 128 + col],           a[0]);
            atomicAdd(&g_y[(size_t)row * 128 + col + 1],       a[1]);
            atomicAdd(&g_y[(size_t)(row + 8) * 128 + col],     a[2]);
            atomicAdd(&g_y[(size_t)(row + 8) * 128 + col + 1], a[3]);
        }
}

// ---------------- stage D: streaming double-buffer, 2 CTAs/SM ----------------
// smem: [A0|B0|A1|B1] = 40960 B
__global__ void __launch_bounds__(256, 2) k_mm_d(float* __restrict__ out) {
    extern __shared__ __align__(128) char dsm[];
    const int row0 = blockIdx.x * 128;
    const int x0   = blockIdx.y * 128;
    const hf* A = g_y_h + (size_t)row0 * 128;
    const hf* B = g_bs_h + (size_t)x0 * 128;
    const int t = threadIdx.x, lane = t & 31, w = t >> 5;
    const int wr = w >> 2, wc = w & 3;
    const uint32_t sb = smem_u32(dsm);
    const int a_off = ((lane & 7) + ((lane >> 3) & 1) * 8) * 80 + ((lane >> 4) & 1) * 16;
    const int b_off = ((lane & 7) + ((lane >> 4) & 1) * 8) * 80 + ((lane >> 3) & 1) * 16;

    float acc[16][4];
#pragma unroll
    for (int i = 0; i < 16; ++i)
#pragma unroll
        for (int q = 0; q < 4; ++q) acc[i][q] = 0.0f;

    issue_tile(sb, A, 128, 0, t);
    issue_tile(sb + TILE_B, B, 128, 0, t);
    cp_commit();

    int cur = 0;
    for (int kt = 0; kt < 4; ++kt) {
        const bool more = (kt + 1 < 4);
        if (more) {
            issue_tile(sb + (cur ^ 1) * 2 * TILE_B, A, 128, (kt + 1) * KT, t);
            issue_tile(sb + (cur ^ 1) * 2 * TILE_B + TILE_B, B, 128, (kt + 1) * KT, t);
            cp_commit();
            cp_wait<1>();
        } else {
            cp_wait<0>();
        }
        __syncthreads();
        compute_ab(sb + cur * 2 * TILE_B, sb + cur * 2 * TILE_B + TILE_B,
                   acc, a_off, b_off, wr, wc);
        __syncthreads();
        cur ^= 1;
    }

#pragma unroll
    for (int mi = 0; mi < 4; ++mi)
#pragma unroll
        for (int ni = 0; ni < 4; ++ni) {
            const int row = row0 + wr * 64 + mi * 16 + (lane >> 2);
            const int col = x0 + wc * 32 + ni * 8 + (lane & 3) * 2;
            const float* a = acc[mi * 4 + ni];
            *(float2*)&out[(size_t)row * NPTS + col]       = make_float2(a[0], a[1]);
            *(float2*)&out[(size_t)(row + 8) * NPTS + col] = make_float2(a[2], a[3]);
        }
}

// ---------------- launch ----------------
extern "C" void kernel_launch(void* const* d_in, const int* in_sizes, int n_in,
                              void* d_out, int out_size) {
    const float* x       = (const float*)d_in[0];
    const float* bases   = (const float*)d_in[1];
    const float* wbases  = (const float*)d_in[2];
    const float* product = (const float*)d_in[3];
    const float* Dout    = (const float*)d_in[4];
    const float* Din     = (const float*)d_in[5];
    const float* Aop     = (const float*)d_in[6];
    const float* Bop     = (const float*)d_in[7];
    const float* weights = (const float*)d_in[8];
    float* out = (float*)d_out;

    cudaFuncSetAttribute(k_mm_a,  cudaFuncAttributeMaxDynamicSharedMemorySize, A_SMEM);
    cudaFuncSetAttribute(k_mm_zy, cudaFuncAttributeMaxDynamicSharedMemorySize, FLAT_SMEM);
    cudaFuncSetAttribute(k_mm_d,  cudaFuncAttributeMaxDynamicSharedMemorySize, 4 * TILE_B);

    prep_kernel<<<2064, 256>>>(Aop, Bop, Dout, Din, product, weights, wbases, bases);
    k_mm_a<<<dim3(16, 16), 256, A_SMEM>>>(x);
    cvt0_kernel<<<256, 256>>>();
    k_mm_zy<<<NB * NJ, 256, FLAT_SMEM>>>();
    cvty_kernel<<<256, 256>>>();
    k_mm_d<<<dim3(16, 128), 256, 4 * TILE_B>>>(out);
}